// round 1
// baseline (speedup 1.0000x reference)
#include <cuda_runtime.h>
#include <math.h>

// Problem constants (fixed by the dataset)
#define BB   256
#define TT   365
#define HH   512
#define DD   32
#define DS   27
#define K3   (3*HH)        // 1536
#define KTOT (DD + HH)     // 544

// Persistent device state (no allocations allowed)
__device__ float g_h[2][BB*HH];   // double-buffered hidden state
__device__ float g_c[BB*HH];      // cell state
__device__ float g_ig[BB*HH];     // static input gate

__device__ __forceinline__ float hsig(float x) {
    return fminf(fmaxf(0.2f*x + 0.5f, 0.0f), 1.0f);
}

// ---------------------------------------------------------------------------
// Init kernel: i_gate = hsig(x_static @ static_kernel + static_bias), h=c=0
// grid = B blocks, block = H threads
// ---------------------------------------------------------------------------
__global__ void init_kernel(const float* __restrict__ x_static,
                            const float* __restrict__ sk,   // [DS, H]
                            const float* __restrict__ sb)   // [H]
{
    int b = blockIdx.x;
    int j = threadIdx.x;            // 0..511
    __shared__ float xs[DS];
    if (j < DS) xs[j] = x_static[b*DS + j];
    __syncthreads();
    float acc = sb[j];
    #pragma unroll
    for (int d = 0; d < DS; d++)
        acc = fmaf(xs[d], sk[d*HH + j], acc);
    int idx = b*HH + j;
    g_ig[idx]   = hsig(acc);
    g_h[0][idx] = 0.0f;
    g_c[idx]    = 0.0f;
}

// ---------------------------------------------------------------------------
// Step kernel: one timestep.
//   z[b, :] = [x_t(b) ; h(b)] @ [Wx ; Wh] + bias    (fused input projection)
//   f,g,o gates -> c,h update -> out[b,t,:]
// Tile: TB=32 batches x TJ=32 units (x 3 gate columns = 96 z-cols per block).
// 128 threads: tn = lane (unit within tile), tb = warp (0..3), each thread
// accumulates 8 batch-rows x 3 gates.
// grid = (HH/TJ, BB/TB) = (16, 8)
// ---------------------------------------------------------------------------
#define TB 32
#define TJ 32
#define NTHREADS 128
#define KC 68                      // 544 = 8 * 68, uniform chunks

__global__ __launch_bounds__(NTHREADS)
void step_kernel(const float* __restrict__ x_dyn,  // [B, T, DD]
                 const float* __restrict__ Wx,     // [DD, 3H]
                 const float* __restrict__ Wh,     // [H, 3H]
                 const float* __restrict__ bias,   // [3H]
                 float* __restrict__ out,          // [B, T, H]
                 int t)
{
    __shared__ float As[TB][KC + 4];     // [row][k] : concat(x_t, h) tile
    __shared__ float Bs[KC][3*TJ];       // [k][col] : weight tile (f|g|o)

    const float* __restrict__ hin  = g_h[t & 1];
    float*       __restrict__ hout = g_h[(t & 1) ^ 1];

    const int tx = threadIdx.x;
    const int tn = tx & 31;              // unit lane
    const int tb = tx >> 5;              // 0..3
    const int j0 = blockIdx.x * TJ;      // unit tile base
    const int b0 = blockIdx.y * TB;      // batch tile base

    float acc[8][3];
    #pragma unroll
    for (int i = 0; i < 8; i++)
        #pragma unroll
        for (int g = 0; g < 3; g++) acc[i][g] = 0.0f;

    #pragma unroll 1
    for (int kbase = 0; kbase < KTOT; kbase += KC) {
        // ---- fill A tile: 32 rows x 68 k-values (float4 loads) ----
        {
            const int NV = TB * KC / 4;          // 544 float4s
            for (int m = tx; m < NV; m += NTHREADS) {
                int kl4 = m % (KC/4);            // 0..16
                int r   = m / (KC/4);
                int k   = kbase + kl4*4;
                float4 v;
                if (k < DD) {
                    v = *reinterpret_cast<const float4*>(
                        &x_dyn[(size_t)(b0 + r)*TT*DD + (size_t)t*DD + k]);
                } else {
                    v = *reinterpret_cast<const float4*>(
                        &hin[(b0 + r)*HH + (k - DD)]);
                }
                *reinterpret_cast<float4*>(&As[r][kl4*4]) = v;
            }
        }
        // ---- fill B tile: 68 k-rows x 96 cols (f|g|o blocks, float4) ----
        {
            const int NV = KC * (3*TJ) / 4;      // 68*24 = 1632 float4s
            for (int m = tx; m < NV; m += NTHREADS) {
                int c4  = m % 24;
                int kk  = m / 24;
                int c   = c4 * 4;                // 0..92
                int gate = c >> 5;               // 0,1,2
                int u    = c & 31;
                int gcol = gate*HH + j0 + u;     // column in [3H]
                int k    = kbase + kk;
                float4 v;
                if (k < DD) v = *reinterpret_cast<const float4*>(&Wx[(size_t)k*K3 + gcol]);
                else        v = *reinterpret_cast<const float4*>(&Wh[(size_t)(k - DD)*K3 + gcol]);
                *reinterpret_cast<float4*>(&Bs[kk][c]) = v;
            }
        }
        __syncthreads();

        // ---- inner product over this k-chunk ----
        #pragma unroll 4
        for (int kc = 0; kc < KC; kc++) {
            float bf = Bs[kc][tn];
            float bg = Bs[kc][32 + tn];
            float bo = Bs[kc][64 + tn];
            #pragma unroll
            for (int i = 0; i < 8; i++) {
                float a = As[tb + 4*i][kc];      // warp-uniform broadcast
                acc[i][0] = fmaf(a, bf, acc[i][0]);
                acc[i][1] = fmaf(a, bg, acc[i][1]);
                acc[i][2] = fmaf(a, bo, acc[i][2]);
            }
        }
        __syncthreads();
    }

    // ---- epilogue: gates, state update, output ----
    const int u  = j0 + tn;
    const float bf = bias[u];
    const float bg = bias[HH + u];
    const float bo = bias[2*HH + u];
    #pragma unroll
    for (int i = 0; i < 8; i++) {
        int b   = b0 + tb + 4*i;
        int idx = b*HH + u;
        float f  = hsig(acc[i][0] + bf);
        float gg = tanhf(acc[i][1] + bg);
        float o  = hsig(acc[i][2] + bo);
        float c  = f * g_c[idx] + g_ig[idx] * gg;
        float h  = o * tanhf(c);
        g_c[idx]  = c;
        hout[idx] = h;
        out[(size_t)b*TT*HH + (size_t)t*HH + u] = h;
    }
}

// ---------------------------------------------------------------------------
// kernel_launch: init + 365 step launches (graph-capturable, no sync/alloc)
// Input order per metadata: x_dyn, x_static, kernel, recurrent_kernel,
//                           bias, static_kernel, static_bias
// ---------------------------------------------------------------------------
extern "C" void kernel_launch(void* const* d_in, const int* in_sizes, int n_in,
                              void* d_out, int out_size)
{
    const float* x_dyn    = (const float*)d_in[0];
    const float* x_static = (const float*)d_in[1];
    const float* Wx       = (const float*)d_in[2];
    const float* Wh       = (const float*)d_in[3];
    const float* bias     = (const float*)d_in[4];
    const float* sk       = (const float*)d_in[5];
    const float* sb       = (const float*)d_in[6];
    float* out = (float*)d_out;

    init_kernel<<<BB, HH>>>(x_static, sk, sb);

    dim3 grid(HH / TJ, BB / TB);   // (16, 8)
    for (int t = 0; t < TT; t++) {
        step_kernel<<<grid, NTHREADS>>>(x_dyn, Wx, Wh, bias, out, t);
    }
}

// round 3
// speedup vs baseline: 1.2300x; 1.2300x over previous
#include <cuda_runtime.h>
#include <cuda_bf16.h>
#include <math.h>
#include <stdint.h>

// Problem constants
#define BB   256
#define TT   365
#define HH   512
#define DD   32
#define K3   1536
#define DS   27

// ---------------- persistent device state ----------------
__device__ __align__(16) __nv_bfloat16 g_Whp_hi[K3 * HH];   // [p][k], p=3u+g
__device__ __align__(16) __nv_bfloat16 g_Whp_lo[K3 * HH];
__device__ __align__(16) __nv_bfloat16 g_Wxp_hi[K3 * 64];   // [p][64], cols 32..63 = 0
__device__ __align__(16) __nv_bfloat16 g_Wxp_lo[K3 * 64];
__device__ __align__(16) __nv_bfloat16 g_x_hi[BB * TT * DD];
__device__ __align__(16) __nv_bfloat16 g_x_lo[BB * TT * DD];
__device__ __align__(16) __nv_bfloat16 g_h_hi[2][BB * HH];
__device__ __align__(16) __nv_bfloat16 g_h_lo[2][BB * HH];
__device__ float g_c[BB * HH];
__device__ float g_ig[BB * HH];

__device__ __forceinline__ float hsig(float x) {
    return fminf(fmaxf(0.2f * x + 0.5f, 0.0f), 1.0f);
}

__device__ __forceinline__ uint32_t smem_u32(const void* p) {
    uint32_t a;
    asm("{ .reg .u64 t; cvta.to.shared.u64 t, %1; cvt.u32.u64 %0, t; }" : "=r"(a) : "l"(p));
    return a;
}

#define LDSM_X4(r0, r1, r2, r3, addr)                                          \
    asm volatile("ldmatrix.sync.aligned.m8n8.x4.shared.b16 {%0,%1,%2,%3}, [%4];" \
                 : "=r"(r0), "=r"(r1), "=r"(r2), "=r"(r3) : "r"(addr))

#define MMA_BF16(d, a0, a1, a2, a3, b0, b1)                                    \
    asm volatile("mma.sync.aligned.m16n8k16.row.col.f32.bf16.bf16.f32 "        \
                 "{%0,%1,%2,%3}, {%4,%5,%6,%7}, {%8,%9}, {%0,%1,%2,%3};"       \
                 : "+f"((d)[0]), "+f"((d)[1]), "+f"((d)[2]), "+f"((d)[3])      \
                 : "r"(a0), "r"(a1), "r"(a2), "r"(a3), "r"(b0), "r"(b1))

#define CP_ASYNC(dst, src, sz) \
    asm volatile("cp.async.cg.shared.global [%0], [%1], 16, %2;" \
                 :: "r"(dst), "l"(src), "r"(sz))
#define CP_COMMIT() asm volatile("cp.async.commit_group;" ::: "memory")
#define CP_WAIT0()  asm volatile("cp.async.wait_group 0;" ::: "memory")

// ---------------- SMEM layout (per stage) ----------------
// A: 64 rows x 64 halves, padded row stride 72 halves (144 B)  -> 9216 B (hi), 9216 B (lo)
// B: 96 rows x 64 halves, stride 144 B                          -> 13824 B x2
#define OFF_AHI   0
#define OFF_ALO   9216
#define OFF_BHI   18432
#define OFF_BLO   32256
#define STAGE_SZ  46080
#define SMEM_TOTAL (2 * STAGE_SZ)   // 92160

// ---------------- init kernels ----------------
__global__ void init_state(const float* __restrict__ x_static,
                           const float* __restrict__ sk,
                           const float* __restrict__ sb) {
    int b = blockIdx.x, j = threadIdx.x;
    __shared__ float xs[DS];
    if (j < DS) xs[j] = x_static[b * DS + j];
    __syncthreads();
    float acc = sb[j];
#pragma unroll
    for (int d = 0; d < DS; d++) acc = fmaf(xs[d], sk[d * HH + j], acc);
    int idx = b * HH + j;
    g_ig[idx] = hsig(acc);
    g_c[idx] = 0.0f;
    __nv_bfloat16 z = __float2bfloat16(0.0f);
    g_h_hi[0][idx] = z;
    g_h_lo[0][idx] = z;
}

__global__ void prep_weights(const float* __restrict__ Wx, const float* __restrict__ Wh) {
    int p = blockIdx.x;                 // p = 3u+g
    int u = p / 3, g = p - 3 * u;
    int col = g * HH + u;
    for (int k = threadIdx.x; k < HH; k += blockDim.x) {
        float w = Wh[(size_t)k * K3 + col];
        __nv_bfloat16 hi = __float2bfloat16(w);
        g_Whp_hi[(size_t)p * HH + k] = hi;
        g_Whp_lo[(size_t)p * HH + k] = __float2bfloat16(w - __bfloat162float(hi));
    }
    if (threadIdx.x < 64) {
        int k = threadIdx.x;
        float w = (k < DD) ? Wx[(size_t)k * K3 + col] : 0.0f;
        __nv_bfloat16 hi = __float2bfloat16(w);
        g_Wxp_hi[p * 64 + k] = hi;
        g_Wxp_lo[p * 64 + k] = __float2bfloat16(w - __bfloat162float(hi));
    }
}

__global__ void prep_x(const float* __restrict__ x_dyn) {
    int i = blockIdx.x * blockDim.x + threadIdx.x;
    if (i >= BB * TT * DD) return;
    float v = x_dyn[i];
    __nv_bfloat16 hi = __float2bfloat16(v);
    g_x_hi[i] = hi;
    g_x_lo[i] = __float2bfloat16(v - __bfloat162float(hi));
}

// ---------------- stage loader (cp.async) ----------------
__device__ __forceinline__ void issue_stage(int j, int t, int m0, int p0,
                                            uint32_t stage_u,
                                            const __nv_bfloat16* hhi,
                                            const __nv_bfloat16* hlo,
                                            int tid) {
    // A tiles: 64 rows x 8 chunks x {hi,lo} = 1024 cp.async
#pragma unroll
    for (int i = tid; i < 1024; i += 256) {
        int buf = i >> 9;
        int rem = i & 511;
        int r = rem >> 3, wq = rem & 7;
        uint32_t dst = stage_u + (buf ? OFF_ALO : OFF_AHI) + r * 144 + wq * 16;
        const __nv_bfloat16* src;
        int sz = 16;
        if (j == 0) {
            const __nv_bfloat16* base = buf ? g_x_lo : g_x_hi;
            src = base + ((size_t)(m0 + r) * TT + t) * DD + (wq & 3) * 8;
            if (wq >= 4) sz = 0;   // zero-fill pad region
        } else {
            const __nv_bfloat16* base = buf ? hlo : hhi;
            src = base + (size_t)(m0 + r) * HH + (j - 1) * 64 + wq * 8;
        }
        CP_ASYNC(dst, src, sz);
    }
    // B tiles: 96 rows x 8 chunks x {hi,lo} = 1536 cp.async
#pragma unroll
    for (int i = tid; i < 1536; i += 256) {
        int buf = (i >= 768);
        int rem = buf ? (i - 768) : i;
        int r = rem >> 3, wq = rem & 7;
        uint32_t dst = stage_u + (buf ? OFF_BLO : OFF_BHI) + r * 144 + wq * 16;
        const __nv_bfloat16* src;
        if (j == 0) {
            const __nv_bfloat16* base = buf ? g_Wxp_lo : g_Wxp_hi;
            src = base + (size_t)(p0 + r) * 64 + wq * 8;
        } else {
            const __nv_bfloat16* base = buf ? g_Whp_lo : g_Whp_hi;
            src = base + (size_t)(p0 + r) * HH + (j - 1) * 64 + wq * 8;
        }
        CP_ASYNC(dst, src, 16);
    }
    CP_COMMIT();
}

// ---------------- step kernel ----------------
// grid = 64: (4 M-tiles of 64 rows) x (16 N-tiles of 32 units = 96 z-cols)
// 256 threads = 8 warps: warp tile 16 rows x 48 cols
__global__ __launch_bounds__(256)
void step_kernel(const float* __restrict__ bias, float* __restrict__ out, int t) {
    extern __shared__ char smem[];
    const uint32_t sm0 = smem_u32(smem);
    const int tid = threadIdx.x;
    const int lane = tid & 31;
    const int wid = tid >> 5;
    const int msub = (wid & 3) * 16;
    const int nsub = (wid >> 2) * 48;

    const int mt = blockIdx.x & 3;
    const int nt = blockIdx.x >> 2;
    const int m0 = mt * 64;
    const int u0 = nt * 32;
    const int p0 = nt * 96;
    const int tpar = t & 1;

    const __nv_bfloat16* __restrict__ hhi = g_h_hi[tpar];
    const __nv_bfloat16* __restrict__ hlo = g_h_lo[tpar];

    float acc[6][4];
#pragma unroll
    for (int i = 0; i < 6; i++)
#pragma unroll
        for (int k = 0; k < 4; k++) acc[i][k] = 0.0f;

    const uint32_t a_off = (msub + (lane & 15)) * 144 + (lane >> 4) * 16;
    const uint32_t b_off = (nsub + ((lane >> 4) & 1) * 8 + (lane & 7)) * 144
                         + ((lane >> 3) & 1) * 16;

    // prologue: stage 0 into buffer 0
    issue_stage(0, t, m0, p0, sm0, hhi, hlo, tid);

#pragma unroll 1
    for (int j = 0; j < 9; j++) {
        CP_WAIT0();
        __syncthreads();
        if (j < 8)
            issue_stage(j + 1, t, m0, p0, sm0 + ((j + 1) & 1) * STAGE_SZ, hhi, hlo, tid);

        const uint32_t su = sm0 + (j & 1) * STAGE_SZ;
#pragma unroll
        for (int pass = 0; pass < 3; pass++) {
            const uint32_t Ab = su + (pass == 2 ? OFF_ALO : OFF_AHI) + a_off;
            const uint32_t Bb = su + (pass == 1 ? OFF_BLO : OFF_BHI) + b_off;
#pragma unroll
            for (int ks = 0; ks < 4; ks++) {
                uint32_t a0, a1, a2, a3;
                LDSM_X4(a0, a1, a2, a3, Ab + ks * 32);
#pragma unroll
                for (int q = 0; q < 3; q++) {
                    uint32_t b0, b1, b2, b3;
                    LDSM_X4(b0, b1, b2, b3, Bb + ks * 32 + q * 2304);
                    MMA_BF16(acc[2 * q + 0], a0, a1, a2, a3, b0, b1);
                    MMA_BF16(acc[2 * q + 1], a0, a1, a2, a3, b2, b3);
                }
            }
        }
    }

    // ---- epilogue: frags -> smem z[64][100] ----
    __syncthreads();
    float* zs = reinterpret_cast<float*>(smem);
#pragma unroll
    for (int nf = 0; nf < 6; nf++) {
        int row = msub + (lane >> 2);
        int col = nsub + nf * 8 + (lane & 3) * 2;
        zs[row * 100 + col]           = acc[nf][0];
        zs[row * 100 + col + 1]       = acc[nf][1];
        zs[(row + 8) * 100 + col]     = acc[nf][2];
        zs[(row + 8) * 100 + col + 1] = acc[nf][3];
    }
    __syncthreads();

    // gates: each thread -> 8 consecutive units of one batch row
    const int bl = tid & 63;
    const int uc = tid >> 6;
    const int b = m0 + bl;
    __nv_bfloat16* __restrict__ hdst_hi = g_h_hi[tpar ^ 1];
    __nv_bfloat16* __restrict__ hdst_lo = g_h_lo[tpar ^ 1];

#pragma unroll
    for (int i = 0; i < 8; i++) {
        int ul = uc * 8 + i;
        int u = u0 + ul;
        int idx = b * HH + u;
        float zf = zs[bl * 100 + 3 * ul + 0] + bias[u];
        float zg = zs[bl * 100 + 3 * ul + 1] + bias[HH + u];
        float zo = zs[bl * 100 + 3 * ul + 2] + bias[2 * HH + u];
        float f = hsig(zf);
        float gg = tanhf(zg);
        float o = hsig(zo);
        float c = f * g_c[idx] + g_ig[idx] * gg;
        float h = o * tanhf(c);
        g_c[idx] = c;
        __nv_bfloat16 hi = __float2bfloat16(h);
        hdst_hi[idx] = hi;
        hdst_lo[idx] = __float2bfloat16(h - __bfloat162float(hi));
        out[(size_t)b * TT * HH + (size_t)t * HH + u] = h;
    }
}

// ---------------- launcher ----------------
extern "C" void kernel_launch(void* const* d_in, const int* in_sizes, int n_in,
                              void* d_out, int out_size) {
    const float* x_dyn    = (const float*)d_in[0];
    const float* x_static = (const float*)d_in[1];
    const float* Wx       = (const float*)d_in[2];
    const float* Wh       = (const float*)d_in[3];
    const float* bias     = (const float*)d_in[4];
    const float* sk       = (const float*)d_in[5];
    const float* sb       = (const float*)d_in[6];
    float* out = (float*)d_out;

    cudaFuncSetAttribute(step_kernel, cudaFuncAttributeMaxDynamicSharedMemorySize, SMEM_TOTAL);

    init_state<<<BB, HH>>>(x_static, sk, sb);
    prep_weights<<<K3, 128>>>(Wx, Wh);
    prep_x<<<(BB * TT * DD + 127) / 128, 128>>>(x_dyn);

    for (int t = 0; t < TT; t++) {
        step_kernel<<<64, 256, SMEM_TOTAL>>>(bias, out, t);
    }
}

// round 4
// speedup vs baseline: 4.6038x; 3.7430x over previous
#include <cuda_runtime.h>
#include <cuda_bf16.h>
#include <math.h>
#include <stdint.h>

#define BB   256
#define TT   365
#define HH   512
#define DD   32
#define K3   1536
#define DS   27
#define NBLK 128

// ---------------- persistent device state ----------------
__device__ __align__(16) __nv_bfloat16 g_Whp_hi[K3 * HH];   // [p][k], p=3u+g
__device__ __align__(16) __nv_bfloat16 g_Whp_lo[K3 * HH];
__device__ __align__(16) __nv_bfloat16 g_Wxp_hi[K3 * DD];   // [p][32]
__device__ __align__(16) __nv_bfloat16 g_Wxp_lo[K3 * DD];
__device__ __align__(16) __nv_bfloat16 g_x_hi[BB * TT * DD];
__device__ __align__(16) __nv_bfloat16 g_x_lo[BB * TT * DD];
__device__ __align__(16) __nv_bfloat16 g_h_hi[2][BB * HH];
__device__ __align__(16) __nv_bfloat16 g_h_lo[2][BB * HH];
__device__ unsigned g_bar_arrive;
__device__ unsigned g_bar_phase;

__device__ __forceinline__ float hsig(float x) {
    return fminf(fmaxf(0.2f * x + 0.5f, 0.0f), 1.0f);
}
__device__ __forceinline__ uint32_t smem_u32(const void* p) {
    uint32_t a;
    asm("{ .reg .u64 t; cvta.to.shared.u64 t, %1; cvt.u32.u64 %0, t; }" : "=r"(a) : "l"(p));
    return a;
}

#define LDSM_X4(r0, r1, r2, r3, addr)                                          \
    asm volatile("ldmatrix.sync.aligned.m8n8.x4.shared.b16 {%0,%1,%2,%3}, [%4];" \
                 : "=r"(r0), "=r"(r1), "=r"(r2), "=r"(r3) : "r"(addr))

#define MMA_BF16(d, a0, a1, a2, a3, b0, b1)                                    \
    asm volatile("mma.sync.aligned.m16n8k16.row.col.f32.bf16.bf16.f32 "        \
                 "{%0,%1,%2,%3}, {%4,%5,%6,%7}, {%8,%9}, {%0,%1,%2,%3};"       \
                 : "+f"((d)[0]), "+f"((d)[1]), "+f"((d)[2]), "+f"((d)[3])      \
                 : "r"(a0), "r"(a1), "r"(a2), "r"(a3), "r"(b0), "r"(b1))

#define CP_ASYNC(dst, src, sz) \
    asm volatile("cp.async.cg.shared.global [%0], [%1], 16, %2;" \
                 :: "r"(dst), "l"(src), "r"(sz))
#define CP_COMMIT() asm volatile("cp.async.commit_group;" ::: "memory")
#define CP_WAIT0()  asm volatile("cp.async.wait_group 0;" ::: "memory")
#define CP_WAIT1()  asm volatile("cp.async.wait_group 1;" ::: "memory")

// ---------------- SMEM layout ----------------
// B rows: 96 z-cols, K=544 halves (1088B) + 16B pad -> stride 1104 (bank step 20)
#define BROW      1104
#define SM_BHI    0
#define SM_BLO    105984          // 96*1104
#define SM_A      211968          // 2 bufs x (hi 4608 + lo 4608) = 18432
#define ABUF_SZ   9216
#define SM_BIAS   230400          // 96 floats
#define SMEM_TOTAL 230784

// ---------------- prep kernels ----------------
__global__ void reset_bar() { g_bar_arrive = 0; g_bar_phase = 0; }

__global__ void prep_weights(const float* __restrict__ Wx, const float* __restrict__ Wh) {
    int p = blockIdx.x;                 // p = 3u+g
    int u = p / 3, g = p - 3 * u;
    int col = g * HH + u;
    for (int k = threadIdx.x; k < HH; k += blockDim.x) {
        float w = Wh[(size_t)k * K3 + col];
        __nv_bfloat16 hi = __float2bfloat16(w);
        g_Whp_hi[(size_t)p * HH + k] = hi;
        g_Whp_lo[(size_t)p * HH + k] = __float2bfloat16(w - __bfloat162float(hi));
    }
    if (threadIdx.x < DD) {
        int k = threadIdx.x;
        float w = Wx[(size_t)k * K3 + col];
        __nv_bfloat16 hi = __float2bfloat16(w);
        g_Wxp_hi[p * DD + k] = hi;
        g_Wxp_lo[p * DD + k] = __float2bfloat16(w - __bfloat162float(hi));
    }
}

__global__ void prep_x(const float* __restrict__ x_dyn) {
    int i = blockIdx.x * blockDim.x + threadIdx.x;
    if (i >= BB * TT * DD) return;
    float v = x_dyn[i];
    __nv_bfloat16 hi = __float2bfloat16(v);
    g_x_hi[i] = hi;
    g_x_lo[i] = __float2bfloat16(v - __bfloat162float(hi));
}

// ---------------- grid barrier (all 128 CTAs resident by construction) ----
__device__ __forceinline__ void grid_bar(unsigned target) {
    __syncthreads();
    if (threadIdx.x == 0) {
        __threadfence();
        unsigned old = atomicAdd(&g_bar_arrive, 1u);
        if (old + 1u == target * NBLK) {
            atomicExch(&g_bar_phase, target);
        } else {
            unsigned p;
            do {
                asm volatile("ld.volatile.global.u32 %0, [%1];" : "=r"(p) : "l"(&g_bar_phase));
            } while (p < target);
        }
        __threadfence();
    }
    __syncthreads();
}

// ---------------- A-chunk loader ----------------
__device__ __forceinline__ void issue_chunk(int j, int t, int m0, uint32_t abase,
                                            const __nv_bfloat16* __restrict__ hhi,
                                            const __nv_bfloat16* __restrict__ hlo,
                                            int tid) {
#pragma unroll
    for (int n = 0; n < 4; n++) {
        int i = tid + n * 128;
        int half = i >> 8;              // 0 hi, 1 lo
        int rem = i & 255;
        int rr = rem >> 3, q = rem & 7;
        uint32_t dst = abase + half * 4608 + rr * 144 + q * 16;
        const __nv_bfloat16* hb = half ? hlo : hhi;
        const __nv_bfloat16* src;
        int sz = 16;
        if (j == 0) {
            if (q < 4) src = (half ? g_x_lo : g_x_hi) + ((size_t)(m0 + rr) * TT + t) * DD + q * 8;
            else       src = hb + (size_t)(m0 + rr) * HH + (q - 4) * 8;
        } else if (j < 8) {
            src = hb + (size_t)(m0 + rr) * HH + 64 * j - 32 + q * 8;
        } else {
            src = hb + (size_t)(m0 + rr) * HH + 480 + (q & 3) * 8;
            if (q >= 4) sz = 0;         // zero-fill tail of half chunk
        }
        CP_ASYNC(dst, src, sz);
    }
    CP_COMMIT();
}

// ---------------- persistent LSTM kernel ----------------
// 128 CTAs x 128 thr. CTA tile: 32 batch rows x 96 z-cols (32 units).
// Warps 2m x 2n, warp tile 16 x 48. c and i_gate live in registers.
__global__ __launch_bounds__(128, 1)
void lstm_persist(const float* __restrict__ x_static,
                  const float* __restrict__ sk,
                  const float* __restrict__ sb,
                  const float* __restrict__ bias,
                  float* __restrict__ out) {
    extern __shared__ char smem[];
    const uint32_t s0 = smem_u32(smem);
    const int tid = threadIdx.x;
    const int lane = tid & 31;
    const int wid = tid >> 5;
    const int mt = blockIdx.x & 7;
    const int nt = blockIdx.x >> 3;
    const int m0 = mt * 32;
    const int u0 = nt * 32;
    const int p0 = nt * 96;

    // ---- one-time: weights into SMEM ----
    for (int i = tid; i < 96 * 68; i += 128) {
        int pl = i / 68, c = i - pl * 68;
        int p = p0 + pl;
        uint4 vh, vl;
        if (c < 4) {
            vh = *reinterpret_cast<const uint4*>(&g_Wxp_hi[p * DD + c * 8]);
            vl = *reinterpret_cast<const uint4*>(&g_Wxp_lo[p * DD + c * 8]);
        } else {
            vh = *reinterpret_cast<const uint4*>(&g_Whp_hi[(size_t)p * HH + (c - 4) * 8]);
            vl = *reinterpret_cast<const uint4*>(&g_Whp_lo[(size_t)p * HH + (c - 4) * 8]);
        }
        *reinterpret_cast<uint4*>(smem + SM_BHI + pl * BROW + c * 16) = vh;
        *reinterpret_cast<uint4*>(smem + SM_BLO + pl * BROW + c * 16) = vl;
    }
    if (tid < 96) {
        int ju = tid / 3, g = tid - 3 * ju;
        reinterpret_cast<float*>(smem + SM_BIAS)[tid] = bias[g * HH + u0 + ju];
    }

    // ---- per-thread state: row r, unit group ug (8 units) ----
    const int r = tid >> 2;
    const int ug = tid & 3;
    float c_reg[8], ig_reg[8];
    {
        float xs[DS];
#pragma unroll
        for (int d = 0; d < DS; d++) xs[d] = x_static[(m0 + r) * DS + d];
#pragma unroll
        for (int i = 0; i < 8; i++) {
            int u = u0 + ug * 8 + i;
            float a = sb[u];
#pragma unroll
            for (int d = 0; d < DS; d++) a = fmaf(xs[d], sk[d * HH + u], a);
            ig_reg[i] = hsig(a);
            c_reg[i] = 0.0f;
            int idx = (m0 + r) * HH + u;
            g_h_hi[0][idx] = __float2bfloat16(0.0f);
            g_h_lo[0][idx] = __float2bfloat16(0.0f);
        }
    }

    unsigned bar_t = 1;
    grid_bar(bar_t++);   // h0 zeroed + weights staged everywhere

    const uint32_t a_off = ((wid & 1) * 16 + (lane & 15)) * 144 + (lane >> 4) * 16;
    const uint32_t b_off = ((wid >> 1) * 48 + ((lane >> 4) & 1) * 8 + (lane & 7)) * BROW
                         + ((lane >> 3) & 1) * 16;
    const float* bias_s = reinterpret_cast<const float*>(smem + SM_BIAS);

#pragma unroll 1
    for (int t = 0; t < TT; t++) {
        const int tpar = t & 1;
        const __nv_bfloat16* __restrict__ hhi = g_h_hi[tpar];
        const __nv_bfloat16* __restrict__ hlo = g_h_lo[tpar];

        float acc[6][4];
#pragma unroll
        for (int i = 0; i < 6; i++)
#pragma unroll
            for (int k = 0; k < 4; k++) acc[i][k] = 0.0f;

        issue_chunk(0, t, m0, s0 + SM_A, hhi, hlo, tid);

#pragma unroll 1
        for (int j = 0; j < 9; j++) {
            if (j > 0) __syncthreads();                 // buf (j+1)&1 free to overwrite
            if (j < 8) {
                issue_chunk(j + 1, t, m0, s0 + SM_A + ((j + 1) & 1) * ABUF_SZ, hhi, hlo, tid);
                CP_WAIT1();
            } else {
                CP_WAIT0();
            }
            __syncthreads();                            // chunk j landed

            const uint32_t Ahi = s0 + SM_A + (j & 1) * ABUF_SZ + a_off;
            const uint32_t Alo = Ahi + 4608;
            const uint32_t Bk = j * 128;
            const int nks = (j < 8) ? 4 : 2;

            for (int ks = 0; ks < nks; ks++) {
                uint32_t ah0, ah1, ah2, ah3, al0, al1, al2, al3;
                uint32_t bh[3][4], bl[3][4];
                LDSM_X4(ah0, ah1, ah2, ah3, Ahi + ks * 32);
                LDSM_X4(al0, al1, al2, al3, Alo + ks * 32);
#pragma unroll
                for (int q = 0; q < 3; q++)
                    LDSM_X4(bh[q][0], bh[q][1], bh[q][2], bh[q][3],
                            s0 + SM_BHI + b_off + Bk + ks * 32 + q * (16 * BROW));
#pragma unroll
                for (int q = 0; q < 3; q++)
                    LDSM_X4(bl[q][0], bl[q][1], bl[q][2], bl[q][3],
                            s0 + SM_BLO + b_off + Bk + ks * 32 + q * (16 * BROW));
#pragma unroll
                for (int q = 0; q < 3; q++) {           // hi x hi
                    MMA_BF16(acc[2 * q + 0], ah0, ah1, ah2, ah3, bh[q][0], bh[q][1]);
                    MMA_BF16(acc[2 * q + 1], ah0, ah1, ah2, ah3, bh[q][2], bh[q][3]);
                }
#pragma unroll
                for (int q = 0; q < 3; q++) {           // hi x lo
                    MMA_BF16(acc[2 * q + 0], ah0, ah1, ah2, ah3, bl[q][0], bl[q][1]);
                    MMA_BF16(acc[2 * q + 1], ah0, ah1, ah2, ah3, bl[q][2], bl[q][3]);
                }
#pragma unroll
                for (int q = 0; q < 3; q++) {           // lo x hi
                    MMA_BF16(acc[2 * q + 0], al0, al1, al2, al3, bh[q][0], bh[q][1]);
                    MMA_BF16(acc[2 * q + 1], al0, al1, al2, al3, bh[q][2], bh[q][3]);
                }
            }
        }

        // ---- epilogue: frags -> smem z (aliases A bufs), then gates ----
        __syncthreads();
        float* zs = reinterpret_cast<float*>(smem + SM_A);
        {
            const int msub = (wid & 1) * 16;
            const int nsub = (wid >> 1) * 48;
#pragma unroll
            for (int nf = 0; nf < 6; nf++) {
                int row = msub + (lane >> 2);
                int col = nsub + nf * 8 + (lane & 3) * 2;
                zs[row * 100 + col]           = acc[nf][0];
                zs[row * 100 + col + 1]       = acc[nf][1];
                zs[(row + 8) * 100 + col]     = acc[nf][2];
                zs[(row + 8) * 100 + col + 1] = acc[nf][3];
            }
        }
        __syncthreads();

        __nv_bfloat16* __restrict__ hdst_hi = g_h_hi[tpar ^ 1];
        __nv_bfloat16* __restrict__ hdst_lo = g_h_lo[tpar ^ 1];
        const float* zr = zs + r * 100 + ug * 24;
        const float* br = bias_s + ug * 24;
#pragma unroll
        for (int i = 0; i < 8; i++) {
            float f  = hsig(zr[3 * i + 0] + br[3 * i + 0]);
            float gg = tanhf(zr[3 * i + 1] + br[3 * i + 1]);
            float o  = hsig(zr[3 * i + 2] + br[3 * i + 2]);
            float c  = f * c_reg[i] + ig_reg[i] * gg;
            float h  = o * tanhf(c);
            c_reg[i] = c;
            int u = u0 + ug * 8 + i;
            int idx = (m0 + r) * HH + u;
            __nv_bfloat16 hi = __float2bfloat16(h);
            hdst_hi[idx] = hi;
            hdst_lo[idx] = __float2bfloat16(h - __bfloat162float(hi));
            out[(size_t)(m0 + r) * TT * HH + (size_t)t * HH + u] = h;
        }

        grid_bar(bar_t++);   // h(t+1) visible everywhere before next step reads
    }
}

// ---------------- launcher ----------------
extern "C" void kernel_launch(void* const* d_in, const int* in_sizes, int n_in,
                              void* d_out, int out_size) {
    const float* x_dyn    = (const float*)d_in[0];
    const float* x_static = (const float*)d_in[1];
    const float* Wx       = (const float*)d_in[2];
    const float* Wh       = (const float*)d_in[3];
    const float* bias     = (const float*)d_in[4];
    const float* sk       = (const float*)d_in[5];
    const float* sb       = (const float*)d_in[6];
    float* out = (float*)d_out;

    cudaFuncSetAttribute(lstm_persist, cudaFuncAttributeMaxDynamicSharedMemorySize, SMEM_TOTAL);

    reset_bar<<<1, 1>>>();
    prep_weights<<<K3, 128>>>(Wx, Wh);
    prep_x<<<(BB * TT * DD + 127) / 128, 128>>>(x_dyn);
    lstm_persist<<<NBLK, 128, SMEM_TOTAL>>>(x_static, sk, sb, bias, out);
}

// round 5
// speedup vs baseline: 4.6645x; 1.0132x over previous
#include <cuda_runtime.h>
#include <cuda_bf16.h>
#include <math.h>
#include <stdint.h>

#define BB   256
#define TT   365
#define HH   512
#define DD   32
#define K3   1536
#define DS   27
#define NBLK 128

// ---------------- persistent device state ----------------
__device__ __align__(16) __nv_bfloat16 g_Whp_hi[K3 * HH];   // [p][k], p=3u+g
__device__ __align__(16) __nv_bfloat16 g_Whp_lo[K3 * HH];
__device__ __align__(16) __nv_bfloat16 g_Wxp_hi[K3 * DD];
__device__ __align__(16) __nv_bfloat16 g_Wxp_lo[K3 * DD];
__device__ __align__(16) __nv_bfloat16 g_x_hi[BB * TT * DD];
__device__ __align__(16) __nv_bfloat16 g_x_lo[BB * TT * DD];
__device__ __align__(16) __nv_bfloat16 g_h_hi[2][BB * HH];
__device__ __align__(16) __nv_bfloat16 g_h_lo[2][BB * HH];
__device__ unsigned g_bar_arrive;
__device__ unsigned g_bar_phase;

__device__ __forceinline__ float hsig(float x) {
    return fminf(fmaxf(0.2f * x + 0.5f, 0.0f), 1.0f);
}
__device__ __forceinline__ uint32_t smem_u32(const void* p) {
    uint32_t a;
    asm("{ .reg .u64 t; cvta.to.shared.u64 t, %1; cvt.u32.u64 %0, t; }" : "=r"(a) : "l"(p));
    return a;
}

#define LDSM_X4(r0, r1, r2, r3, addr)                                          \
    asm volatile("ldmatrix.sync.aligned.m8n8.x4.shared.b16 {%0,%1,%2,%3}, [%4];" \
                 : "=r"(r0), "=r"(r1), "=r"(r2), "=r"(r3) : "r"(addr))
#define LDSM_X2(r0, r1, addr)                                                  \
    asm volatile("ldmatrix.sync.aligned.m8n8.x2.shared.b16 {%0,%1}, [%2];"     \
                 : "=r"(r0), "=r"(r1) : "r"(addr))

#define MMA_BF16(d, a0, a1, a2, a3, b0, b1)                                    \
    asm volatile("mma.sync.aligned.m16n8k16.row.col.f32.bf16.bf16.f32 "        \
                 "{%0,%1,%2,%3}, {%4,%5,%6,%7}, {%8,%9}, {%0,%1,%2,%3};"       \
                 : "+f"((d)[0]), "+f"((d)[1]), "+f"((d)[2]), "+f"((d)[3])      \
                 : "r"(a0), "r"(a1), "r"(a2), "r"(a3), "r"(b0), "r"(b1))

#define CP_ASYNC(dst, src, sz) \
    asm volatile("cp.async.cg.shared.global [%0], [%1], 16, %2;" \
                 :: "r"(dst), "l"(src), "r"(sz))
#define CP_COMMIT() asm volatile("cp.async.commit_group;" ::: "memory")
#define CP_WAIT0()  asm volatile("cp.async.wait_group 0;" ::: "memory")
#define CP_WAIT1()  asm volatile("cp.async.wait_group 1;" ::: "memory")

// ---------------- SMEM layout ----------------
#define BROW      1104            // 544*2 + 16B pad
#define SM_BHI    0
#define SM_BLO    105984
#define SM_A      211968          // 2 bufs x (hi 4608 + lo 4608)
#define ABUF_SZ   9216
#define SM_BIAS   230400
#define SMEM_TOTAL 230784

// ---------------- prep kernels ----------------
__global__ void reset_bar() { g_bar_arrive = 0; g_bar_phase = 0; }

__global__ void prep_weights(const float* __restrict__ Wx, const float* __restrict__ Wh) {
    int p = blockIdx.x;                 // p = 3u+g
    int u = p / 3, g = p - 3 * u;
    int col = g * HH + u;
    for (int k = threadIdx.x; k < HH; k += blockDim.x) {
        float w = Wh[(size_t)k * K3 + col];
        __nv_bfloat16 hi = __float2bfloat16(w);
        g_Whp_hi[(size_t)p * HH + k] = hi;
        g_Whp_lo[(size_t)p * HH + k] = __float2bfloat16(w - __bfloat162float(hi));
    }
    if (threadIdx.x < DD) {
        int k = threadIdx.x;
        float w = Wx[(size_t)k * K3 + col];
        __nv_bfloat16 hi = __float2bfloat16(w);
        g_Wxp_hi[p * DD + k] = hi;
        g_Wxp_lo[p * DD + k] = __float2bfloat16(w - __bfloat162float(hi));
    }
}

__global__ void prep_x(const float* __restrict__ x_dyn) {
    int i = blockIdx.x * blockDim.x + threadIdx.x;
    if (i >= BB * TT * DD) return;
    float v = x_dyn[i];
    __nv_bfloat16 hi = __float2bfloat16(v);
    g_x_hi[i] = hi;
    g_x_lo[i] = __float2bfloat16(v - __bfloat162float(hi));
}

// ---------------- grid barrier ----------------
__device__ __forceinline__ void grid_bar(unsigned target) {
    __syncthreads();
    if (threadIdx.x == 0) {
        __threadfence();
        unsigned old = atomicAdd(&g_bar_arrive, 1u);
        if (old + 1u == target * NBLK) {
            atomicExch(&g_bar_phase, target);
        } else {
            unsigned p;
            do {
                asm volatile("ld.volatile.global.u32 %0, [%1];" : "=r"(p) : "l"(&g_bar_phase));
            } while (p < target);
        }
        __threadfence();
    }
    __syncthreads();
}

// ---------------- A-chunk loader (256 threads, 512 cp.async) ----------------
__device__ __forceinline__ void issue_chunk(int j, int t, int m0, uint32_t abase,
                                            const __nv_bfloat16* __restrict__ hhi,
                                            const __nv_bfloat16* __restrict__ hlo,
                                            int tid) {
#pragma unroll
    for (int n = 0; n < 2; n++) {
        int i = tid + n * 256;
        int half = i >> 8;              // 0 hi, 1 lo
        int rem = i & 255;
        int rr = rem >> 3, q = rem & 7;
        uint32_t dst = abase + half * 4608 + rr * 144 + q * 16;
        const __nv_bfloat16* hb = half ? hlo : hhi;
        const __nv_bfloat16* src;
        int sz = 16;
        if (j == 0) {
            if (q < 4) src = (half ? g_x_lo : g_x_hi) + ((size_t)(m0 + rr) * TT + t) * DD + q * 8;
            else       src = hb + (size_t)(m0 + rr) * HH + (q - 4) * 8;
        } else if (j < 8) {
            src = hb + (size_t)(m0 + rr) * HH + 64 * j - 32 + q * 8;
        } else {
            src = hb + (size_t)(m0 + rr) * HH + 480 + (q & 3) * 8;
            if (q >= 4) sz = 0;
        }
        CP_ASYNC(dst, src, sz);
    }
    CP_COMMIT();
}

// ---------------- persistent LSTM kernel ----------------
// 128 CTAs x 256 thr (8 warps). CTA tile 32 rows x 96 z-cols.
// Warp grid 2m x 4n, warp tile 16 x 24.
__global__ __launch_bounds__(256, 1)
void lstm_persist(const float* __restrict__ x_static,
                  const float* __restrict__ sk,
                  const float* __restrict__ sb,
                  const float* __restrict__ bias,
                  float* __restrict__ out) {
    extern __shared__ char smem[];
    const uint32_t s0 = smem_u32(smem);
    const int tid = threadIdx.x;
    const int lane = tid & 31;
    const int wid = tid >> 5;
    const int mt = blockIdx.x & 7;
    const int nt = blockIdx.x >> 3;
    const int m0 = mt * 32;
    const int u0 = nt * 32;
    const int p0 = nt * 96;

    // ---- one-time: weights into SMEM ----
    for (int i = tid; i < 96 * 68; i += 256) {
        int pl = i / 68, c = i - pl * 68;
        int p = p0 + pl;
        uint4 vh, vl;
        if (c < 4) {
            vh = *reinterpret_cast<const uint4*>(&g_Wxp_hi[p * DD + c * 8]);
            vl = *reinterpret_cast<const uint4*>(&g_Wxp_lo[p * DD + c * 8]);
        } else {
            vh = *reinterpret_cast<const uint4*>(&g_Whp_hi[(size_t)p * HH + (c - 4) * 8]);
            vl = *reinterpret_cast<const uint4*>(&g_Whp_lo[(size_t)p * HH + (c - 4) * 8]);
        }
        *reinterpret_cast<uint4*>(smem + SM_BHI + pl * BROW + c * 16) = vh;
        *reinterpret_cast<uint4*>(smem + SM_BLO + pl * BROW + c * 16) = vl;
    }
    if (tid < 96) {
        int ju = tid / 3, g = tid - 3 * ju;
        reinterpret_cast<float*>(smem + SM_BIAS)[tid] = bias[g * HH + u0 + ju];
    }

    // ---- per-thread state: row r (0..31), unit group ug (0..7) x 4 units ----
    const int r = tid >> 3;
    const int ug = tid & 7;
    float c_reg[4], ig_reg[4];
    {
        float xs[DS];
#pragma unroll
        for (int d = 0; d < DS; d++) xs[d] = x_static[(m0 + r) * DS + d];
#pragma unroll
        for (int i = 0; i < 4; i++) {
            int u = u0 + ug * 4 + i;
            float a = sb[u];
#pragma unroll
            for (int d = 0; d < DS; d++) a = fmaf(xs[d], sk[d * HH + u], a);
            ig_reg[i] = hsig(a);
            c_reg[i] = 0.0f;
            int idx = (m0 + r) * HH + u;
            g_h_hi[0][idx] = __float2bfloat16(0.0f);
            g_h_lo[0][idx] = __float2bfloat16(0.0f);
        }
    }

    unsigned bar_t = 1;
    grid_bar(bar_t++);

    // A frag addr: 16 rows (m half), x4
    const int msub = (wid & 1) * 16;
    const int nsub = (wid >> 1) * 24;
    const uint32_t a_off = (msub + (lane & 15)) * 144 + (lane >> 4) * 16;
    // B x4 frag: rows nsub..nsub+15
    const uint32_t b4_off = (nsub + ((lane >> 4) & 1) * 8 + (lane & 7)) * BROW
                          + ((lane >> 3) & 1) * 16;
    // B x2 frag: rows nsub+16..nsub+23 (lanes 0..15 supply addrs)
    const uint32_t b2_off = (nsub + 16 + (lane & 7)) * BROW + ((lane >> 3) & 1) * 16;
    const float* bias_s = reinterpret_cast<const float*>(smem + SM_BIAS);

#pragma unroll 1
    for (int t = 0; t < TT; t++) {
        const int tpar = t & 1;
        const __nv_bfloat16* __restrict__ hhi = g_h_hi[tpar];
        const __nv_bfloat16* __restrict__ hlo = g_h_lo[tpar];

        float acc[3][4];
#pragma unroll
        for (int i = 0; i < 3; i++)
#pragma unroll
            for (int k = 0; k < 4; k++) acc[i][k] = 0.0f;

        issue_chunk(0, t, m0, s0 + SM_A, hhi, hlo, tid);

#pragma unroll 1
        for (int j = 0; j < 9; j++) {
            if (j > 0) __syncthreads();
            if (j < 8) {
                issue_chunk(j + 1, t, m0, s0 + SM_A + ((j + 1) & 1) * ABUF_SZ, hhi, hlo, tid);
                CP_WAIT1();
            } else {
                CP_WAIT0();
            }
            __syncthreads();

            const uint32_t Ahi = s0 + SM_A + (j & 1) * ABUF_SZ + a_off;
            const uint32_t Alo = Ahi + 4608;
            const uint32_t Bk = j * 128;
            const int nks = (j < 8) ? 4 : 2;

            for (int ks = 0; ks < nks; ks++) {
                uint32_t ah0, ah1, ah2, ah3, al0, al1, al2, al3;
                uint32_t bh[6], bl[6];
                LDSM_X4(ah0, ah1, ah2, ah3, Ahi + ks * 32);
                LDSM_X4(al0, al1, al2, al3, Alo + ks * 32);
                LDSM_X4(bh[0], bh[1], bh[2], bh[3], s0 + SM_BHI + b4_off + Bk + ks * 32);
                LDSM_X2(bh[4], bh[5],               s0 + SM_BHI + b2_off + Bk + ks * 32);
                LDSM_X4(bl[0], bl[1], bl[2], bl[3], s0 + SM_BLO + b4_off + Bk + ks * 32);
                LDSM_X2(bl[4], bl[5],               s0 + SM_BLO + b2_off + Bk + ks * 32);
                // hi x hi
                MMA_BF16(acc[0], ah0, ah1, ah2, ah3, bh[0], bh[1]);
                MMA_BF16(acc[1], ah0, ah1, ah2, ah3, bh[2], bh[3]);
                MMA_BF16(acc[2], ah0, ah1, ah2, ah3, bh[4], bh[5]);
                // hi x lo
                MMA_BF16(acc[0], ah0, ah1, ah2, ah3, bl[0], bl[1]);
                MMA_BF16(acc[1], ah0, ah1, ah2, ah3, bl[2], bl[3]);
                MMA_BF16(acc[2], ah0, ah1, ah2, ah3, bl[4], bl[5]);
                // lo x hi
                MMA_BF16(acc[0], al0, al1, al2, al3, bh[0], bh[1]);
                MMA_BF16(acc[1], al0, al1, al2, al3, bh[2], bh[3]);
                MMA_BF16(acc[2], al0, al1, al2, al3, bh[4], bh[5]);
            }
        }

        // ---- epilogue: frags -> smem z[32][100] (aliases A bufs) ----
        __syncthreads();
        float* zs = reinterpret_cast<float*>(smem + SM_A);
#pragma unroll
        for (int nf = 0; nf < 3; nf++) {
            int row = msub + (lane >> 2);
            int col = nsub + nf * 8 + (lane & 3) * 2;
            zs[row * 100 + col]           = acc[nf][0];
            zs[row * 100 + col + 1]       = acc[nf][1];
            zs[(row + 8) * 100 + col]     = acc[nf][2];
            zs[(row + 8) * 100 + col + 1] = acc[nf][3];
        }
        __syncthreads();

        __nv_bfloat16* __restrict__ hdst_hi = g_h_hi[tpar ^ 1];
        __nv_bfloat16* __restrict__ hdst_lo = g_h_lo[tpar ^ 1];
        const float* zr = zs + r * 100 + ug * 12;
        const float* br = bias_s + ug * 12;
        float hv[4];
#pragma unroll
        for (int i = 0; i < 4; i++) {
            float f  = hsig(zr[3 * i + 0] + br[3 * i + 0]);
            float gg = tanhf(zr[3 * i + 1] + br[3 * i + 1]);
            float o  = hsig(zr[3 * i + 2] + br[3 * i + 2]);
            float c  = f * c_reg[i] + ig_reg[i] * gg;
            float h  = o * tanhf(c);
            c_reg[i] = c;
            hv[i] = h;
        }
        {
            int u = u0 + ug * 4;
            int idx = (m0 + r) * HH + u;
            __nv_bfloat162 hhp, hlp;
            __nv_bfloat16 h0 = __float2bfloat16(hv[0]);
            __nv_bfloat16 h1 = __float2bfloat16(hv[1]);
            __nv_bfloat16 h2 = __float2bfloat16(hv[2]);
            __nv_bfloat16 h3 = __float2bfloat16(hv[3]);
            hhp.x = h0; hhp.y = h1;
            *reinterpret_cast<__nv_bfloat162*>(&hdst_hi[idx]) = hhp;
            hhp.x = h2; hhp.y = h3;
            *reinterpret_cast<__nv_bfloat162*>(&hdst_hi[idx + 2]) = hhp;
            hlp.x = __float2bfloat16(hv[0] - __bfloat162float(h0));
            hlp.y = __float2bfloat16(hv[1] - __bfloat162float(h1));
            *reinterpret_cast<__nv_bfloat162*>(&hdst_lo[idx]) = hlp;
            hlp.x = __float2bfloat16(hv[2] - __bfloat162float(h2));
            hlp.y = __float2bfloat16(hv[3] - __bfloat162float(h3));
            *reinterpret_cast<__nv_bfloat162*>(&hdst_lo[idx + 2]) = hlp;
            float4 ov = make_float4(hv[0], hv[1], hv[2], hv[3]);
            *reinterpret_cast<float4*>(&out[(size_t)(m0 + r) * TT * HH + (size_t)t * HH + u]) = ov;
        }

        grid_bar(bar_t++);
    }
}

// ---------------- launcher ----------------
extern "C" void kernel_launch(void* const* d_in, const int* in_sizes, int n_in,
                              void* d_out, int out_size) {
    const float* x_dyn    = (const float*)d_in[0];
    const float* x_static = (const float*)d_in[1];
    const float* Wx       = (const float*)d_in[2];
    const float* Wh       = (const float*)d_in[3];
    const float* bias     = (const float*)d_in[4];
    const float* sk       = (const float*)d_in[5];
    const float* sb       = (const float*)d_in[6];
    float* out = (float*)d_out;

    cudaFuncSetAttribute(lstm_persist, cudaFuncAttributeMaxDynamicSharedMemorySize, SMEM_TOTAL);

    reset_bar<<<1, 1>>>();
    prep_weights<<<K3, 128>>>(Wx, Wh);
    prep_x<<<(BB * TT * DD + 127) / 128, 128>>>(x_dyn);
    lstm_persist<<<NBLK, 256, SMEM_TOTAL>>>(x_static, sk, sb, bias, out);
}

// round 6
// speedup vs baseline: 4.9284x; 1.0566x over previous
#include <cuda_runtime.h>
#include <cuda_bf16.h>
#include <math.h>
#include <stdint.h>

#define BB   256
#define TT   365
#define HH   512
#define DD   32
#define K3   1536
#define DS   27
#define NBLK 128
#define KTOT 544

// ---------------- persistent device state ----------------
// Merged weight staging: row P = nt*96 + g*32 + ul, k in [0,544) = [x(32) ; h(512)]
__device__ __align__(16) __nv_bfloat16 g_Wp_hi[K3 * KTOT];
__device__ __align__(16) __nv_bfloat16 g_Wp_lo[K3 * KTOT];
__device__ __align__(16) __nv_bfloat16 g_x_hi[BB * TT * DD];
__device__ __align__(16) __nv_bfloat16 g_x_lo[BB * TT * DD];
__device__ __align__(16) __nv_bfloat16 g_h_hi[2][BB * HH];
__device__ __align__(16) __nv_bfloat16 g_h_lo[2][BB * HH];
__device__ unsigned g_grp_cnt[8 * 32];      // 128B stride per group
__device__ volatile unsigned g_grp_phase[8 * 32];

__device__ __forceinline__ float hsig(float x) {
    return fminf(fmaxf(0.2f * x + 0.5f, 0.0f), 1.0f);
}
__device__ __forceinline__ float ftanh(float x) {
    float t = __expf(-2.0f * fabsf(x));
    return copysignf(__fdividef(1.0f - t, 1.0f + t), x);
}
__device__ __forceinline__ uint32_t smem_u32(const void* p) {
    uint32_t a;
    asm("{ .reg .u64 t; cvta.to.shared.u64 t, %1; cvt.u32.u64 %0, t; }" : "=r"(a) : "l"(p));
    return a;
}

#define LDSM_X4(r0, r1, r2, r3, addr)                                          \
    asm volatile("ldmatrix.sync.aligned.m8n8.x4.shared.b16 {%0,%1,%2,%3}, [%4];" \
                 : "=r"(r0), "=r"(r1), "=r"(r2), "=r"(r3) : "r"(addr))

#define MMA_BF16(d, a0, a1, a2, a3, b0, b1)                                    \
    asm volatile("mma.sync.aligned.m16n8k16.row.col.f32.bf16.bf16.f32 "        \
                 "{%0,%1,%2,%3}, {%4,%5,%6,%7}, {%8,%9}, {%0,%1,%2,%3};"       \
                 : "+f"((d)[0]), "+f"((d)[1]), "+f"((d)[2]), "+f"((d)[3])      \
                 : "r"(a0), "r"(a1), "r"(a2), "r"(a3), "r"(b0), "r"(b1))

#define CP_ASYNC(dst, src, sz) \
    asm volatile("cp.async.cg.shared.global [%0], [%1], 16, %2;" \
                 :: "r"(dst), "l"(src), "r"(sz))
#define CP_COMMIT() asm volatile("cp.async.commit_group;" ::: "memory")
#define CP_WAIT0()  asm volatile("cp.async.wait_group 0;" ::: "memory")
#define CP_WAIT1()  asm volatile("cp.async.wait_group 1;" ::: "memory")

// ---------------- SMEM layout ----------------
#define BROW      1104            // 544*2 + 16B pad
#define SM_BHI    0
#define SM_BLO    105984
#define SM_A      211968          // 2 bufs x (hi 4608 + lo 4608)
#define ABUF_SZ   9216
#define SMEM_TOTAL 230400

// ---------------- prep kernels ----------------
__global__ void reset_bar() {
    if (threadIdx.x < 8 * 32) {
        g_grp_cnt[threadIdx.x] = 0;
        g_grp_phase[threadIdx.x] = 0;
    }
}

__global__ void prep_weights(const float* __restrict__ Wx, const float* __restrict__ Wh) {
    int P = blockIdx.x;                 // P = nt*96 + g*32 + ul
    int nt = P / 96, rq = P - nt * 96;
    int g = rq >> 5, ul = rq & 31;
    int col = g * HH + nt * 32 + ul;
    for (int k = threadIdx.x; k < KTOT; k += blockDim.x) {
        float w = (k < DD) ? Wx[(size_t)k * K3 + col]
                           : Wh[(size_t)(k - DD) * K3 + col];
        __nv_bfloat16 hi = __float2bfloat16(w);
        g_Wp_hi[(size_t)P * KTOT + k] = hi;
        g_Wp_lo[(size_t)P * KTOT + k] = __float2bfloat16(w - __bfloat162float(hi));
    }
}

__global__ void prep_x(const float* __restrict__ x_dyn) {
    int i = blockIdx.x * blockDim.x + threadIdx.x;
    if (i >= BB * TT * DD) return;
    float v = x_dyn[i];
    __nv_bfloat16 hi = __float2bfloat16(v);
    g_x_hi[i] = hi;
    g_x_lo[i] = __float2bfloat16(v - __bfloat162float(hi));
}

// ---------------- group barrier: 16 CTAs sharing mt ----------------
__device__ __forceinline__ void grid_bar_grp(int mt, unsigned target) {
    __syncthreads();
    if (threadIdx.x == 0) {
        __threadfence();
        unsigned old = atomicAdd(&g_grp_cnt[mt * 32], 1u);
        if (old + 1u == target * 16u) {
            atomicExch((unsigned*)&g_grp_phase[mt * 32], target);
        } else {
            unsigned p;
            do {
                asm volatile("ld.volatile.global.u32 %0, [%1];"
                             : "=r"(p) : "l"((const unsigned*)&g_grp_phase[mt * 32]));
            } while (p < target);
        }
        __threadfence();
    }
    __syncthreads();
}

// ---------------- A-chunk loader (256 threads) ----------------
__device__ __forceinline__ void issue_chunk(int j, int t, int m0, uint32_t abase,
                                            const __nv_bfloat16* __restrict__ hhi,
                                            const __nv_bfloat16* __restrict__ hlo,
                                            int tid) {
#pragma unroll
    for (int n = 0; n < 2; n++) {
        int i = tid + n * 256;
        int half = i >> 8;              // 0 hi, 1 lo
        int rem = i & 255;
        int rr = rem >> 3, q = rem & 7;
        uint32_t dst = abase + half * 4608 + rr * 144 + q * 16;
        const __nv_bfloat16* hb = half ? hlo : hhi;
        const __nv_bfloat16* src;
        int sz = 16;
        if (j == 0) {
            if (q < 4) src = (half ? g_x_lo : g_x_hi) + ((size_t)(m0 + rr) * TT + t) * DD + q * 8;
            else       src = hb + (size_t)(m0 + rr) * HH + (q - 4) * 8;
        } else if (j < 8) {
            src = hb + (size_t)(m0 + rr) * HH + 64 * j - 32 + q * 8;
        } else {
            src = hb + (size_t)(m0 + rr) * HH + 480 + (q & 3) * 8;
            if (q >= 4) sz = 0;
        }
        CP_ASYNC(dst, src, sz);
    }
    CP_COMMIT();
}

// ---------------- persistent LSTM kernel ----------------
// 128 CTAs x 256 thr. CTA tile 32 rows x 32 units (96 z-cols, q = g*32+u).
// Warp (wid&1 -> m half 16 rows, wq=wid>>1 -> 8-unit span, all 3 gates).
__global__ __launch_bounds__(256, 1)
void lstm_persist(const float* __restrict__ x_static,
                  const float* __restrict__ sk,
                  const float* __restrict__ sb,
                  const float* __restrict__ bias,
                  float* __restrict__ out) {
    extern __shared__ char smem[];
    const uint32_t s0 = smem_u32(smem);
    const int tid = threadIdx.x;
    const int lane = tid & 31;
    const int wid = tid >> 5;
    const int msub = (wid & 1) * 16;
    const int wq8 = (wid >> 1) * 8;
    const int mt = blockIdx.x & 7;
    const int nt = blockIdx.x >> 3;
    const int m0 = mt * 32;
    const int u0 = nt * 32;

    // ---- one-time: weights into SMEM (rows q = g*32+ul for this nt) ----
    for (int i = tid; i < 96 * 68; i += 256) {
        int pl = i / 68, c = i - pl * 68;
        size_t src = (size_t)(nt * 96 + pl) * KTOT + c * 8;
        *reinterpret_cast<uint4*>(smem + SM_BHI + pl * BROW + c * 16) =
            *reinterpret_cast<const uint4*>(&g_Wp_hi[src]);
        *reinterpret_cast<uint4*>(smem + SM_BLO + pl * BROW + c * 16) =
            *reinterpret_cast<const uint4*>(&g_Wp_lo[src]);
    }

    // ---- per-thread ownership: rows gr0, gr1; units uA, uA+1 ----
    const int gr0 = m0 + msub + (lane >> 2);
    const int gr1 = gr0 + 8;
    const int uA = u0 + wq8 + (lane & 3) * 2;

    const float bf0 = bias[uA],          bf1 = bias[uA + 1];
    const float bg0 = bias[HH + uA],     bg1 = bias[HH + uA + 1];
    const float bo0 = bias[2 * HH + uA], bo1 = bias[2 * HH + uA + 1];

    float c_reg[4] = {0.f, 0.f, 0.f, 0.f};
    float ig_reg[4];
    {
#pragma unroll
        for (int i = 0; i < 4; i++) {
            int row = (i < 2) ? gr0 : gr1;
            int u = uA + (i & 1);
            float a = sb[u];
#pragma unroll
            for (int d = 0; d < DS; d++)
                a = fmaf(x_static[row * DS + d], sk[d * HH + u], a);
            ig_reg[i] = hsig(a);
        }
        __nv_bfloat162 z2; z2.x = __float2bfloat16(0.f); z2.y = z2.x;
        *reinterpret_cast<__nv_bfloat162*>(&g_h_hi[0][gr0 * HH + uA]) = z2;
        *reinterpret_cast<__nv_bfloat162*>(&g_h_hi[0][gr1 * HH + uA]) = z2;
        *reinterpret_cast<__nv_bfloat162*>(&g_h_lo[0][gr0 * HH + uA]) = z2;
        *reinterpret_cast<__nv_bfloat162*>(&g_h_lo[0][gr1 * HH + uA]) = z2;
    }

    unsigned bar_t = 1;
    grid_bar_grp(mt, bar_t++);

    // ---- ldmatrix lane addresses ----
    const uint32_t a_off = (msub + (lane & 15)) * 144 + (lane >> 4) * 16;
    const int oct = lane >> 3, l8 = lane & 7;
    const uint32_t koff = (oct & 1) * 16;
    // X4 #1: [f_hi k0, f_hi k8, g_hi k0, g_hi k8]
    const uint32_t bA = s0 + SM_BHI + ((oct < 2 ? wq8 : 32 + wq8) + l8) * BROW + koff;
    // X4 #2: [o_hi k0, o_hi k8, f_lo k0, f_lo k8]
    const uint32_t bB = (oct < 2 ? s0 + SM_BHI + (64 + wq8 + l8) * BROW
                                 : s0 + SM_BLO + (wq8 + l8) * BROW) + koff;
    // X4 #3: [g_lo k0, g_lo k8, o_lo k0, o_lo k8]
    const uint32_t bC = s0 + SM_BLO + ((oct < 2 ? 32 : 64) + wq8 + l8) * BROW + koff;

#pragma unroll 1
    for (int t = 0; t < TT; t++) {
        const int tpar = t & 1;
        const __nv_bfloat16* __restrict__ hhi = g_h_hi[tpar];
        const __nv_bfloat16* __restrict__ hlo = g_h_lo[tpar];

        float acc[3][4];
#pragma unroll
        for (int i = 0; i < 3; i++)
#pragma unroll
            for (int k = 0; k < 4; k++) acc[i][k] = 0.f;

        issue_chunk(0, t, m0, s0 + SM_A, hhi, hlo, tid);

#pragma unroll 1
        for (int j = 0; j < 9; j++) {
            if (j > 0) __syncthreads();
            if (j < 8) {
                issue_chunk(j + 1, t, m0, s0 + SM_A + ((j + 1) & 1) * ABUF_SZ, hhi, hlo, tid);
                CP_WAIT1();
            } else {
                CP_WAIT0();
            }
            __syncthreads();

            const uint32_t Ahi = s0 + SM_A + (j & 1) * ABUF_SZ + a_off;
            const uint32_t Alo = Ahi + 4608;
            const uint32_t Bk = j * 128;
            const int nks = (j < 8) ? 4 : 2;

            for (int ks = 0; ks < nks; ks++) {
                uint32_t ah0, ah1, ah2, ah3, al0, al1, al2, al3;
                uint32_t p0, p1, p2, p3, q0, q1, q2, q3, r0, r1, r2, r3;
                LDSM_X4(ah0, ah1, ah2, ah3, Ahi + ks * 32);
                LDSM_X4(al0, al1, al2, al3, Alo + ks * 32);
                LDSM_X4(p0, p1, p2, p3, bA + Bk + ks * 32);
                LDSM_X4(q0, q1, q2, q3, bB + Bk + ks * 32);
                LDSM_X4(r0, r1, r2, r3, bC + Bk + ks * 32);
                // hi x hi
                MMA_BF16(acc[0], ah0, ah1, ah2, ah3, p0, p1);
                MMA_BF16(acc[1], ah0, ah1, ah2, ah3, p2, p3);
                MMA_BF16(acc[2], ah0, ah1, ah2, ah3, q0, q1);
                // hi x lo
                MMA_BF16(acc[0], ah0, ah1, ah2, ah3, q2, q3);
                MMA_BF16(acc[1], ah0, ah1, ah2, ah3, r0, r1);
                MMA_BF16(acc[2], ah0, ah1, ah2, ah3, r2, r3);
                // lo x hi
                MMA_BF16(acc[0], al0, al1, al2, al3, p0, p1);
                MMA_BF16(acc[1], al0, al1, al2, al3, p2, p3);
                MMA_BF16(acc[2], al0, al1, al2, al3, q0, q1);
            }
        }

        // ---- register epilogue: thread owns f/g/o for its 4 (row,unit) ----
        float hv[4];
        {
            float f, gg, o, c;
            f  = hsig(acc[0][0] + bf0);
            gg = ftanh(acc[1][0] + bg0);
            o  = hsig(acc[2][0] + bo0);
            c = f * c_reg[0] + ig_reg[0] * gg; c_reg[0] = c; hv[0] = o * ftanh(c);
            f  = hsig(acc[0][1] + bf1);
            gg = ftanh(acc[1][1] + bg1);
            o  = hsig(acc[2][1] + bo1);
            c = f * c_reg[1] + ig_reg[1] * gg; c_reg[1] = c; hv[1] = o * ftanh(c);
            f  = hsig(acc[0][2] + bf0);
            gg = ftanh(acc[1][2] + bg0);
            o  = hsig(acc[2][2] + bo0);
            c = f * c_reg[2] + ig_reg[2] * gg; c_reg[2] = c; hv[2] = o * ftanh(c);
            f  = hsig(acc[0][3] + bf1);
            gg = ftanh(acc[1][3] + bg1);
            o  = hsig(acc[2][3] + bo1);
            c = f * c_reg[3] + ig_reg[3] * gg; c_reg[3] = c; hv[3] = o * ftanh(c);
        }

        __nv_bfloat16* __restrict__ hdst_hi = g_h_hi[tpar ^ 1];
        __nv_bfloat16* __restrict__ hdst_lo = g_h_lo[tpar ^ 1];
        {
            __nv_bfloat16 h0 = __float2bfloat16(hv[0]);
            __nv_bfloat16 h1 = __float2bfloat16(hv[1]);
            __nv_bfloat16 h2 = __float2bfloat16(hv[2]);
            __nv_bfloat16 h3 = __float2bfloat16(hv[3]);
            __nv_bfloat162 ph; ph.x = h0; ph.y = h1;
            *reinterpret_cast<__nv_bfloat162*>(&hdst_hi[gr0 * HH + uA]) = ph;
            ph.x = h2; ph.y = h3;
            *reinterpret_cast<__nv_bfloat162*>(&hdst_hi[gr1 * HH + uA]) = ph;
            __nv_bfloat162 pl;
            pl.x = __float2bfloat16(hv[0] - __bfloat162float(h0));
            pl.y = __float2bfloat16(hv[1] - __bfloat162float(h1));
            *reinterpret_cast<__nv_bfloat162*>(&hdst_lo[gr0 * HH + uA]) = pl;
            pl.x = __float2bfloat16(hv[2] - __bfloat162float(h2));
            pl.y = __float2bfloat16(hv[3] - __bfloat162float(h3));
            *reinterpret_cast<__nv_bfloat162*>(&hdst_lo[gr1 * HH + uA]) = pl;
            float2 ov0 = make_float2(hv[0], hv[1]);
            float2 ov1 = make_float2(hv[2], hv[3]);
            *reinterpret_cast<float2*>(&out[(size_t)gr0 * TT * HH + (size_t)t * HH + uA]) = ov0;
            *reinterpret_cast<float2*>(&out[(size_t)gr1 * TT * HH + (size_t)t * HH + uA]) = ov1;
        }

        grid_bar_grp(mt, bar_t++);
    }
}

// ---------------- launcher ----------------
extern "C" void kernel_launch(void* const* d_in, const int* in_sizes, int n_in,
                              void* d_out, int out_size) {
    const float* x_dyn    = (const float*)d_in[0];
    const float* x_static = (const float*)d_in[1];
    const float* Wx       = (const float*)d_in[2];
    const float* Wh       = (const float*)d_in[3];
    const float* bias     = (const float*)d_in[4];
    const float* sk       = (const float*)d_in[5];
    const float* sb       = (const float*)d_in[6];
    float* out = (float*)d_out;

    cudaFuncSetAttribute(lstm_persist, cudaFuncAttributeMaxDynamicSharedMemorySize, SMEM_TOTAL);

    reset_bar<<<1, 256>>>();
    prep_weights<<<K3, 128>>>(Wx, Wh);
    prep_x<<<(BB * TT * DD + 127) / 128, 128>>>(x_dyn);
    lstm_persist<<<NBLK, 256, SMEM_TOTAL>>>(x_static, sk, sb, bias, out);
}